// round 1
// baseline (speedup 1.0000x reference)
#include <cuda_runtime.h>
#include <cstdint>

#define BATCH 256
#define NN 256
#define MM 256
#define DIM 32
#define BIGF 1e8f
#define XPAD 260                       // floats per transposed-x row (mult of 4, 16B aligned)
#define RING_FLOATS (3 * 8 * 1024)     // 3 band slots x 8 tiles x 1024 floats = 96KB
#define BUF_STRIDE 264
#define SMEM_DP ((RING_FLOATS + 3 * BUF_STRIDE) * 4)

// dist in 32x32-tiled layout: [b][tile= (i>>5)*8+(j>>5)][ (i&31)*32 + (j&31) ]
__device__ float g_dist[BATCH * NN * MM];
__device__ float g_partial[BATCH];

__device__ __forceinline__ unsigned long long pack2f(float a, float b) {
    unsigned long long r;
    asm("mov.b64 %0, {%1, %2};" : "=l"(r) : "f"(a), "f"(b));
    return r;
}
__device__ __forceinline__ unsigned long long fma2f(unsigned long long a,
                                                    unsigned long long b,
                                                    unsigned long long c) {
    unsigned long long d;
    asm("fma.rn.f32x2 %0, %1, %2, %3;" : "=l"(d) : "l"(a), "l"(b), "l"(c));
    return d;
}
__device__ __forceinline__ float lo32(unsigned long long v) {
    return __uint_as_float((unsigned)(v & 0xffffffffull));
}
__device__ __forceinline__ float hi32(unsigned long long v) {
    return __uint_as_float((unsigned)(v >> 32));
}

// ---------------------------------------------------------------------------
// Kernel 1: squared-distance matrix per batch, written in tiled layout.
// One block per batch; thread t owns column j=t (y row in registers, packed
// f32x2 for dual-rate FMA). x is staged transposed in shared so (i,i+1,i+2,i+3)
// are contiguous — LDS.128 broadcast, zero conflicts.
// ---------------------------------------------------------------------------
__global__ __launch_bounds__(256) void dist_kernel(const float* __restrict__ x,
                                                   const float* __restrict__ y) {
    __shared__ float xsT[DIM * XPAD];
    __shared__ float x2s[NN];
    const int b = blockIdx.x, t = threadIdx.x;
    const float* xb = x + (size_t)b * NN * DIM;
    const float* yb = y + (size_t)b * MM * DIM + t * DIM;

    for (int e = t; e < NN * DIM; e += 256) {
        int i = e >> 5, k = e & 31;
        xsT[k * XPAD + i] = xb[e];
    }

    unsigned long long yp[DIM];
    float y2 = 0.f;
#pragma unroll
    for (int k = 0; k < DIM; k++) {
        float v = yb[k];
        yp[k] = pack2f(v, v);
        y2 = fmaf(v, v, y2);
    }
    __syncthreads();

    {   // x row norms (one-time, conflicts irrelevant)
        float s = 0.f;
#pragma unroll 8
        for (int k = 0; k < DIM; k++) { float v = xsT[k * XPAD + t]; s = fmaf(v, v, s); }
        x2s[t] = s;
    }
    __syncthreads();

    float* gb = g_dist + (size_t)b * NN * MM;
    const int ct = t >> 5, jj = t & 31;

    for (int i0 = 0; i0 < NN; i0 += 4) {
        unsigned long long a01 = 0ull, a23 = 0ull;
#pragma unroll
        for (int k = 0; k < DIM; k++) {
            ulonglong2 xv = *(const ulonglong2*)(xsT + k * XPAD + i0);
            a01 = fma2f(xv.x, yp[k], a01);
            a23 = fma2f(xv.y, yp[k], a23);
        }
        float d0 = lo32(a01), d1 = hi32(a01), d2 = lo32(a23), d3 = hi32(a23);
        float4 xx = *(const float4*)(x2s + i0);
        float r0 = fmaxf(xx.x + y2 - 2.f * d0, 0.f);
        float r1 = fmaxf(xx.y + y2 - 2.f * d1, 0.f);
        float r2 = fmaxf(xx.z + y2 - 2.f * d2, 0.f);
        float r3 = fmaxf(xx.w + y2 - 2.f * d3, 0.f);
        int base = ((i0 >> 5) * 8 + ct) * 1024 + ((i0 & 31) << 5) + jj;
        gb[base] = r0; gb[base + 32] = r1; gb[base + 64] = r2; gb[base + 96] = r3;
    }
}

// ---------------------------------------------------------------------------
// Kernel 2: anti-diagonal wavefront DP. One block per batch, thread t owns
// column j=t+1. dist tiles stream through a 3-slot shared ring via cp.async
// (tile-antidiagonal bands), reads from the ring are bank-conflict-free
// (bank == lane). `up` is register-carried.
// ---------------------------------------------------------------------------
__device__ __forceinline__ void issue_band(int T, const float* gb, uint32_t ringS, int t) {
    if (T > 14) return;
    int slot = T % 3;
    int rt0 = T - 7 > 0 ? T - 7 : 0;
    int rt1 = T < 7 ? T : 7;
    for (int rt = rt0; rt <= rt1; rt++) {
        int ctile = T - rt;
        const float* g = gb + (rt * 8 + ctile) * 1024 + t * 4;
        uint32_t s = ringS + (uint32_t)((slot * 8192 + (rt & 7) * 1024 + t * 4) * 4);
        asm volatile("cp.async.cg.shared.global [%0], [%1], 16;" :: "r"(s), "l"(g));
    }
}

__global__ __launch_bounds__(256) void dtw_kernel() {
    extern __shared__ float sm[];
    float* ring = sm;
    float* buf  = sm + RING_FLOATS;
    const int b = blockIdx.x, t = threadIdx.x, j = t + 1;

    float* bA = buf;                 // diag p-2 (init: p=0)
    float* bB = buf + BUF_STRIDE;    // diag p-1 (init: p=1)
    float* bC = buf + 2 * BUF_STRIDE;

    for (int idx = t; idx < 3 * BUF_STRIDE; idx += 256) buf[idx] = BIGF;
    if (t == 0) bA[0] = 0.f;   // D[0][0]

    const float* gb = g_dist + (size_t)b * NN * MM;
    uint32_t ringS = (uint32_t)__cvta_generic_to_shared(ring);

    issue_band(0, gb, ringS, t);
    asm volatile("cp.async.commit_group;");

    float* cur2 = bA; float* cur1 = bB; float* cur0 = bC;
    float myprev = BIGF;

    for (int p = 2; p <= NN + MM; ++p) {
        int q = p - 2;
        if ((q & 31) == 0) {
            int T = q >> 5;
            issue_band(T + 1, gb, ringS, t);
            asm volatile("cp.async.commit_group;");
            asm volatile("cp.async.wait_group 1;");
            __syncthreads();   // band T visible to all; also covers buffer init at p=2
        }

        int i = p - j;
        float nv = BIGF;
        if (i >= 1 && i <= NN) {
            int r = i - 1, c = t;                 // c = j-1
            int rt = r >> 5, ctile = c >> 5;
            float dq = ring[((rt + ctile) % 3) * 8192 + (rt & 7) * 1024 +
                            ((r & 31) << 5) + (c & 31)];
            float lf = cur1[t];                   // D[i][j-1]
            float dg = cur2[t];                   // D[i-1][j-1]
            float up = myprev;                    // D[i-1][j] (register-carried)
            float mn = fminf(fminf(up, lf), dg);
            float s  = __expf(mn - up) + __expf(mn - lf) + __expf(mn - dg);
            nv = dq + mn - __logf(s);
            cur0[j] = nv;
        }
        if (j == p) cur0[j] = BIGF;   // top border D[0][p] (only while p<=MM)
        if (t == 0) cur0[0] = BIGF;   // left border D[p][0]
        myprev = nv;
        if (p == NN + MM && t == 255) g_partial[b] = nv;
        __syncthreads();
        float* tmp = cur2; cur2 = cur1; cur1 = cur0; cur0 = tmp;
    }
}

// ---------------------------------------------------------------------------
// Kernel 3: mean over batches -> scalar output.
// ---------------------------------------------------------------------------
__global__ __launch_bounds__(256) void reduce_kernel(float* __restrict__ out) {
    __shared__ float sb[256];
    int t = threadIdx.x;
    sb[t] = g_partial[t];
    __syncthreads();
    for (int s = 128; s > 0; s >>= 1) {
        if (t < s) sb[t] += sb[t + s];
        __syncthreads();
    }
    if (t == 0) out[0] = sb[0] * (1.0f / BATCH);
}

extern "C" void kernel_launch(void* const* d_in, const int* in_sizes, int n_in,
                              void* d_out, int out_size) {
    (void)in_sizes; (void)n_in; (void)out_size;
    const float* x = (const float*)d_in[0];
    const float* y = (const float*)d_in[1];
    float* out = (float*)d_out;

    cudaFuncSetAttribute(dtw_kernel, cudaFuncAttributeMaxDynamicSharedMemorySize, SMEM_DP);

    dist_kernel<<<BATCH, 256>>>(x, y);
    dtw_kernel<<<BATCH, 256, SMEM_DP>>>();
    reduce_kernel<<<1, 256>>>(out);
}

// round 2
// speedup vs baseline: 1.0441x; 1.0441x over previous
#include <cuda_runtime.h>
#include <cstdint>

#define BATCH 256
#define NN 256
#define MM 256
#define DIM 32
#define BIGF 1e8f
#define XP 132                 // xsT pitch (floats)
#define YP 68                  // ysT pitch (floats)
#define RING_FLOATS (4 * 4096) // 4 slots x 16 tiles x 256 floats = 64KB
#define BUF_STRIDE 264
#define SMEM_DP ((RING_FLOATS + 3 * BUF_STRIDE) * 4)

// dist in 16x16-tiled layout: [b][tile = (r>>4)*16 + (c>>4)][ (r&15)*16 + (c&15) ]
__device__ float g_dist[BATCH * NN * MM];
__device__ float g_partial[BATCH];

typedef unsigned long long u64;

__device__ __forceinline__ u64 pack2f(float a, float b) {
    u64 r;
    asm("mov.b64 %0, {%1, %2};" : "=l"(r) : "f"(a), "f"(b));
    return r;
}
__device__ __forceinline__ u64 fma2f(u64 a, u64 b, u64 c) {
    u64 d;
    asm("fma.rn.f32x2 %0, %1, %2, %3;" : "=l"(d) : "l"(a), "l"(b), "l"(c));
    return d;
}
__device__ __forceinline__ float lo32(u64 v) {
    return __uint_as_float((unsigned)(v & 0xffffffffull));
}
__device__ __forceinline__ float hi32(u64 v) {
    return __uint_as_float((unsigned)(v >> 32));
}

// ---------------------------------------------------------------------------
// Kernel 1: tiled GEMM distance. Grid = BATCH * 8 (2 i-tiles x 4 j-tiles of
// a 128x64 block tile). 256 threads as 16x16; each thread computes an 8x4
// register tile with packed f32x2 FMAs (i-pairs packed). Output written as
// 16x16 tiles (coalesced float4 stores).
// ---------------------------------------------------------------------------
__global__ __launch_bounds__(256) void dist_kernel(const float* __restrict__ x,
                                                   const float* __restrict__ y) {
    __shared__ float xsT[DIM * XP];
    __shared__ float ysT[DIM * YP];
    __shared__ float x2s[128];
    __shared__ float y2s[64];

    const int bx = blockIdx.x;
    const int b = bx >> 3, sub = bx & 7;
    const int ibase = (sub >> 2) * 128, jbase = (sub & 3) * 64;
    const int t = threadIdx.x;

    const float* xb = x + ((size_t)b * NN + ibase) * DIM;
    const float* yb = y + ((size_t)b * MM + jbase) * DIM;

    for (int e = t; e < 128 * DIM; e += 256) xsT[(e & 31) * XP + (e >> 5)] = xb[e];
    for (int e = t; e < 64 * DIM; e += 256) ysT[(e & 31) * YP + (e >> 5)] = yb[e];
    __syncthreads();

    if (t < 128) {
        float s = 0.f;
#pragma unroll 8
        for (int k = 0; k < DIM; k++) { float v = xsT[k * XP + t]; s = fmaf(v, v, s); }
        x2s[t] = s;
    } else if (t < 192) {
        int j = t - 128;
        float s = 0.f;
#pragma unroll 8
        for (int k = 0; k < DIM; k++) { float v = ysT[k * YP + j]; s = fmaf(v, v, s); }
        y2s[j] = s;
    }
    __syncthreads();

    const int ti = t >> 4, tj = t & 15;
    const int i0 = ti * 8, j0 = tj * 4;

    u64 acc[4][4];
#pragma unroll
    for (int a = 0; a < 4; a++)
#pragma unroll
        for (int q = 0; q < 4; q++) acc[a][q] = 0ull;

#pragma unroll 8
    for (int k = 0; k < DIM; k++) {
        ulonglong2 xv = *(const ulonglong2*)(xsT + k * XP + i0);
        ulonglong2 xw = *(const ulonglong2*)(xsT + k * XP + i0 + 4);
        float4 yv = *(const float4*)(ysT + k * YP + j0);
        u64 yp0 = pack2f(yv.x, yv.x), yp1 = pack2f(yv.y, yv.y);
        u64 yp2 = pack2f(yv.z, yv.z), yp3 = pack2f(yv.w, yv.w);
        acc[0][0] = fma2f(xv.x, yp0, acc[0][0]);
        acc[0][1] = fma2f(xv.x, yp1, acc[0][1]);
        acc[0][2] = fma2f(xv.x, yp2, acc[0][2]);
        acc[0][3] = fma2f(xv.x, yp3, acc[0][3]);
        acc[1][0] = fma2f(xv.y, yp0, acc[1][0]);
        acc[1][1] = fma2f(xv.y, yp1, acc[1][1]);
        acc[1][2] = fma2f(xv.y, yp2, acc[1][2]);
        acc[1][3] = fma2f(xv.y, yp3, acc[1][3]);
        acc[2][0] = fma2f(xw.x, yp0, acc[2][0]);
        acc[2][1] = fma2f(xw.x, yp1, acc[2][1]);
        acc[2][2] = fma2f(xw.x, yp2, acc[2][2]);
        acc[2][3] = fma2f(xw.x, yp3, acc[2][3]);
        acc[3][0] = fma2f(xw.y, yp0, acc[3][0]);
        acc[3][1] = fma2f(xw.y, yp1, acc[3][1]);
        acc[3][2] = fma2f(xw.y, yp2, acc[3][2]);
        acc[3][3] = fma2f(xw.y, yp3, acc[3][3]);
    }

    float* gb = g_dist + (size_t)b * (NN * MM);
    const int c0 = jbase + j0;
    const int ctile = c0 >> 4, cin = c0 & 15;
    float w0 = y2s[j0], w1 = y2s[j0 + 1], w2 = y2s[j0 + 2], w3 = y2s[j0 + 3];

#pragma unroll
    for (int ip = 0; ip < 4; ip++) {
        int rlA = i0 + 2 * ip, rlB = rlA + 1;
        int rA = ibase + rlA, rB = rA + 1;
        float xA = x2s[rlA], xB = x2s[rlB];
        float4 vA, vB;
        vA.x = fmaxf(fmaf(-2.f, lo32(acc[ip][0]), xA + w0), 0.f);
        vA.y = fmaxf(fmaf(-2.f, lo32(acc[ip][1]), xA + w1), 0.f);
        vA.z = fmaxf(fmaf(-2.f, lo32(acc[ip][2]), xA + w2), 0.f);
        vA.w = fmaxf(fmaf(-2.f, lo32(acc[ip][3]), xA + w3), 0.f);
        vB.x = fmaxf(fmaf(-2.f, hi32(acc[ip][0]), xB + w0), 0.f);
        vB.y = fmaxf(fmaf(-2.f, hi32(acc[ip][1]), xB + w1), 0.f);
        vB.z = fmaxf(fmaf(-2.f, hi32(acc[ip][2]), xB + w2), 0.f);
        vB.w = fmaxf(fmaf(-2.f, hi32(acc[ip][3]), xB + w3), 0.f);
        *(float4*)(gb + ((rA >> 4) * 16 + ctile) * 256 + ((rA & 15) << 4) + cin) = vA;
        *(float4*)(gb + ((rB >> 4) * 16 + ctile) * 256 + ((rB & 15) << 4) + cin) = vB;
    }
}

// ---------------------------------------------------------------------------
// Kernel 2: anti-diagonal wavefront DP. One block per batch, thread t owns
// column j=t+1. dist streams through a 4-slot ring of 16-diagonal sub-bands
// (16 tiles of 16x16 = 16KB per band) via cp.async. Softmin uses the exact
// median trick: s = 1 + exp(mn-mid) + exp(mn-mx)  (3 MUFU instead of 4).
// ---------------------------------------------------------------------------
__device__ __forceinline__ void issue_band(int T, const float* gb, uint32_t ringS, int t) {
    if (T > 30) return;
    int rt0 = T - 15 > 0 ? T - 15 : 0;
    int rt1 = T < 15 ? T : 15;
    int chunks = (rt1 - rt0 + 1) * 64;   // 16B chunks in this band
    uint32_t slotbase = ringS + (uint32_t)((T & 3) * 4096 * 4);
    for (int n = t; n < chunks; n += 256) {
        int tile = n >> 6, wi = n & 63;
        int rt = rt0 + tile;
        const float* g = gb + ((rt * 16 + (T - rt)) * 256 + wi * 4);
        uint32_t s = slotbase + (uint32_t)(((rt & 15) * 256 + wi * 4) * 4);
        asm volatile("cp.async.cg.shared.global [%0], [%1], 16;" :: "r"(s), "l"(g));
    }
}

__global__ __launch_bounds__(256) void dtw_kernel() {
    extern __shared__ float sm[];
    float* ring = sm;
    float* buf  = sm + RING_FLOATS;
    const int b = blockIdx.x, t = threadIdx.x, j = t + 1;

    float* bA = buf;                  // diag p-2
    float* bB = buf + BUF_STRIDE;     // diag p-1
    float* bC = buf + 2 * BUF_STRIDE;

    for (int idx = t; idx < 3 * BUF_STRIDE; idx += 256) buf[idx] = BIGF;
    if (t == 0) bA[0] = 0.f;   // D[0][0]

    const float* gb = g_dist + (size_t)b * (NN * MM);
    uint32_t ringS = (uint32_t)__cvta_generic_to_shared(ring);

    issue_band(0, gb, ringS, t);
    asm volatile("cp.async.commit_group;");

    float* cur2 = bA; float* cur1 = bB; float* cur0 = bC;
    float myprev = BIGF;

    for (int p = 2; p <= NN + MM; ++p) {
        int q = p - 2;
        if ((q & 15) == 0) {
            int U = q >> 4;
            issue_band(U + 1, gb, ringS, t);
            asm volatile("cp.async.commit_group;");
            asm volatile("cp.async.wait_group 1;");
            __syncthreads();   // band U visible; also covers buffer init at p=2
        }

        int i = p - j;
        float nv = BIGF;
        if (i >= 1 && i <= NN) {
            int r = i - 1, c = t;
            int rt = r >> 4, ct = c >> 4;
            float dq = ring[((rt + ct) & 3) * 4096 + (rt & 15) * 256 +
                            ((r & 15) << 4) + (c & 15)];
            float lf = cur1[t];                  // D[i][j-1]
            float dg = cur2[t];                  // D[i-1][j-1]
            float up = myprev;                   // D[i-1][j]
            float mn = fminf(fminf(up, lf), dg);
            float mx = fmaxf(fmaxf(up, lf), dg);
            float md = fmaxf(fminf(up, lf), fminf(fmaxf(up, lf), dg));  // exact median
            float s  = 1.0f + __expf(mn - md) + __expf(mn - mx);
            nv = dq + mn - __logf(s);
            cur0[j] = nv;
        }
        if (j == p) cur0[j] = BIGF;   // top border D[0][p]
        if (t == 0) cur0[0] = BIGF;   // left border D[p][0]
        myprev = nv;
        if (p == NN + MM && t == 255) g_partial[b] = nv;
        __syncthreads();
        float* tmp = cur2; cur2 = cur1; cur1 = cur0; cur0 = tmp;
    }
}

// ---------------------------------------------------------------------------
// Kernel 3: mean over batches -> scalar output.
// ---------------------------------------------------------------------------
__global__ __launch_bounds__(256) void reduce_kernel(float* __restrict__ out) {
    __shared__ float sb[256];
    int t = threadIdx.x;
    sb[t] = g_partial[t];
    __syncthreads();
    for (int s = 128; s > 0; s >>= 1) {
        if (t < s) sb[t] += sb[t + s];
        __syncthreads();
    }
    if (t == 0) out[0] = sb[0] * (1.0f / BATCH);
}

extern "C" void kernel_launch(void* const* d_in, const int* in_sizes, int n_in,
                              void* d_out, int out_size) {
    (void)in_sizes; (void)n_in; (void)out_size;
    const float* x = (const float*)d_in[0];
    const float* y = (const float*)d_in[1];
    float* out = (float*)d_out;

    cudaFuncSetAttribute(dtw_kernel, cudaFuncAttributeMaxDynamicSharedMemorySize, SMEM_DP);

    dist_kernel<<<BATCH * 8, 256>>>(x, y);
    dtw_kernel<<<BATCH, 256, SMEM_DP>>>();
    reduce_kernel<<<1, 256>>>(out);
}